// round 14
// baseline (speedup 1.0000x reference)
#include <cuda_runtime.h>
#include <cuda_bf16.h>

// ---------------------------------------------------------------------------
// YOLO loss reduction: 1024 x 28 x 28 cells -> 5 scalars.
// Round 14: mask-predicated loads.  The ~4.1 TB/s read wall is real (invariant
// across LDG depth / TMA / prefetch), so the lever is BYTES: ~50% of cells are
// masked and need only their 2 conf channels.  Load mask first, then predicate
// pred/tcls/tbox loads per-float4 -- predicated-off LDGs skip whole DRAM
// sectors.  Zero-fill is safe: masked IoU -> NaN -> sanitized by the valid
// check -> exact 0 contribution (== reference's m*(...)=0).
// ---------------------------------------------------------------------------

#define NTILES   3136        // 802816 / 256
#define TPB      256
#define INV_S    0.0357142857142857f   // 1/28
#define N_BATCH  1024.0

__device__ double       g_acc[4];   // cls, nbj, reg, cobj raw sums (zero-init)
__device__ unsigned int g_count;    // finished-block ticket (zero-init)

__global__ void __launch_bounds__(TPB) yolo_main_k(
    const float* __restrict__ pred,   // [802816, 30]
    const float* __restrict__ tbox,   // [802816, 4]
    const float* __restrict__ tcls,   // [802816, 20]
    const unsigned int* __restrict__ mask,  // [802816] words, truth <=> w != 0
    float*       __restrict__ out)
{
    __shared__ __align__(16) float sp[TPB * 30];   // staged pred tile
    __shared__ float smk[TPB];                     // mask as float
    __shared__ float red[8][4];

    const int tid   = threadIdx.x;
    const int cell0 = blockIdx.x * TPB;

    // --- phase 0: mask first (drives all load predicates) -------------------
    smk[tid] = (mask[cell0 + tid] != 0u) ? 1.0f : 0.0f;
    __syncthreads();

    const float m = smk[tid];

    // --- pred staging, PREDICATED per float4 --------------------------------
    // float4 i covers tile-floats 4i..4i+3.  Needed iff it touches an unmasked
    // cell, or touches conf channels (ch4/ch9) of a masked cell.  Skipped
    // float4s are zero-filled (safe, see header).
    {
        const float4* p4  = (const float4*)(pred + (size_t)cell0 * 30);
        float4*       sp4 = (float4*)sp;
        for (int i = tid; i < 1920; i += TPB) {
            int f0 = 4 * i;
            int c0 = f0 / 30;
            int r0 = f0 - c0 * 30;          // starting channel within cell c0
            int hi0 = (r0 + 3 <= 29) ? r0 + 3 : 29;
            bool need = (smk[c0] != 0.0f)
                     || (4 >= r0 && 4 <= hi0)
                     || (9 >= r0 && 9 <= hi0);
            if (!need && r0 + 3 > 29) {
                // wraps into cell c0+1 (channels 0..r0-27; never reaches ch4)
                need = (smk[c0 + 1] != 0.0f);
            }
            float4 v = need ? p4[i] : make_float4(0.f, 0.f, 0.f, 0.f);
            sp4[i] = v;
        }
    }

    // --- tcls, PREDICATED on the owning cell's mask --------------------------
    float4 tc[5];
    int    tcl[5];
    {
        const float4* tcg4 = (const float4*)(tcls + (size_t)cell0 * 20);
        #pragma unroll
        for (int j = 0; j < 5; j++) {
            int e4 = tid + TPB * j;
            int cl = e4 / 5;
            tcl[j] = e4;
            tc[j] = (smk[cl] != 0.0f) ? tcg4[e4]
                                      : make_float4(0.f, 0.f, 0.f, 0.f);
        }
    }

    // --- tbox, PREDICATED on own mask ----------------------------------------
    const float4 tbv = (m != 0.0f) ? ((const float4*)tbox)[cell0 + tid]
                                   : make_float4(0.f, 0.f, 0.f, 0.f);

    __syncthreads();   // sp visible

    // --- class loss: registers (tc) vs shared pred ---------------------------
    float acc_cls = 0.0f;
    #pragma unroll
    for (int j = 0; j < 5; j++) {
        int e4 = tcl[j];
        int cl = e4 / 5;
        int ch = 4 * (e4 - cl * 5);
        const float* pc = sp + cl * 30 + 10 + ch;
        float mm = smk[cl];
        float d0 = pc[0] - tc[j].x;
        float d1 = pc[1] - tc[j].y;
        float d2 = pc[2] - tc[j].z;
        float d3 = pc[3] - tc[j].w;
        acc_cls += mm * (d0 * d0 + d1 * d1 + d2 * d2 + d3 * d3);
    }

    // --- per-cell box terms ---------------------------------------------------
    const float* p = sp + tid * 30;

    float tcx = tbv.x * INV_S, tcy = tbv.y * INV_S;
    float thw = 0.5f * tbv.z, thh = 0.5f * tbv.w;
    float tbx1 = tcx - thw, tby1 = tcy - thh;
    float tbx2 = tcx + thw, tby2 = tcy + thh;
    float ta = (tbx2 - tbx1) * (tby2 - tby1);

    float bx1[2], by1[2], bx2[2], by2[2], iou[2], cf[2];
    #pragma unroll
    for (int b = 0; b < 2; b++) {
        float x = p[5 * b + 0], y = p[5 * b + 1];
        float w = p[5 * b + 2], h = p[5 * b + 3];
        cf[b] = p[5 * b + 4];
        float cx = x * INV_S, cy = y * INV_S;
        float hw = 0.5f * w, hh = 0.5f * h;
        bx1[b] = cx - hw; by1[b] = cy - hh;
        bx2[b] = cx + hw; by2[b] = cy + hh;
        float ltx = fmaxf(bx1[b], tbx1), lty = fmaxf(by1[b], tby1);
        float rbx = fminf(bx2[b], tbx2), rby = fminf(by2[b], tby2);
        float wi = fmaxf(rbx - ltx, 0.0f), hi = fmaxf(rby - lty, 0.0f);
        float inter = wi * hi;
        float a1 = (bx2[b] - bx1[b]) * (by2[b] - by1[b]);
        iou[b] = inter / (a1 + ta - inter);   // masked cells: 0/0 = NaN
    }

    int best = (iou[1] > iou[0]) ? 1 : 0;   // first max wins (jnp.argmax)
    float biou = iou[best];
    float bbx1 = bx1[best], bby1 = by1[best];
    float bbx2 = bx2[best], bby2 = by2[best];
    float bconf = cf[best];
    if (!(biou > 0.0f)) {                   // sanitizes NaN too
        bbx1 = bby1 = bbx2 = bby2 = 0.0f;
        bconf = 0.0f; biou = 0.0f;
    }

    float dx = bbx1 - tbx1, dy = bby1 - tby1;
    float lxy = dx * dx + dy * dy;
    float s1 = (bbx2 > 0.0f) ? sqrtf(bbx2) : 0.0f;
    float s2 = (bby2 > 0.0f) ? sqrtf(bby2) : 0.0f;
    float t1 = (tbx2 > 0.0f) ? sqrtf(tbx2) : 0.0f;
    float t2 = (tby2 > 0.0f) ? sqrtf(tby2) : 0.0f;
    float dw = s1 - t1, dh = s2 - t2;
    float lwh = dw * dw + dh * dh;

    float acc_reg  = m * (lxy + lwh);
    float dc       = bconf - biou;
    float acc_cobj = m * dc * dc;
    float acc_nbj  = (1.0f - m) * (cf[0] * cf[0] + cf[1] * cf[1]);

    // --- reduction: warp shuffle -> shared -> double atomics -----------------
    float a4[4] = { acc_cls, acc_nbj, acc_reg, acc_cobj };
    #pragma unroll
    for (int j = 0; j < 4; j++) {
        #pragma unroll
        for (int o = 16; o; o >>= 1)
            a4[j] += __shfl_down_sync(0xffffffffu, a4[j], o);
    }
    int warp = tid >> 5, lane = tid & 31;
    if (lane == 0) {
        red[warp][0] = a4[0]; red[warp][1] = a4[1];
        red[warp][2] = a4[2]; red[warp][3] = a4[3];
    }
    __syncthreads();
    if (tid == 0) {
        double s[4] = {0.0, 0.0, 0.0, 0.0};
        #pragma unroll
        for (int w = 0; w < 8; w++)
            for (int j = 0; j < 4; j++) s[j] += (double)red[w][j];
        atomicAdd(&g_acc[0], s[0]);
        atomicAdd(&g_acc[1], s[1]);
        atomicAdd(&g_acc[2], s[2]);
        atomicAdd(&g_acc[3], s[3]);

        __threadfence();
        unsigned int ticket = atomicAdd(&g_count, 1u);
        if (ticket == NTILES - 1) {
            double cls  = atomicAdd(&g_acc[0], 0.0);
            double nbj  = atomicAdd(&g_acc[1], 0.0);
            double reg  = atomicAdd(&g_acc[2], 0.0);
            double cobj = atomicAdd(&g_acc[3], 0.0);
            double cls_l  = 2.0 * cls / N_BATCH;
            double nbj_l  = 0.5 * nbj / N_BATCH;
            double reg_l  = 5.0 * reg / N_BATCH;
            double cobj_l = cobj / N_BATCH;
            out[0] = (float)(cls_l + nbj_l + reg_l + cobj_l);
            out[1] = (float)reg_l;
            out[2] = (float)cobj_l;
            out[3] = (float)nbj_l;
            out[4] = (float)cls_l;
            // self-reset for the next graph replay
            atomicExch((unsigned long long*)&g_acc[0], 0ull);
            atomicExch((unsigned long long*)&g_acc[1], 0ull);
            atomicExch((unsigned long long*)&g_acc[2], 0ull);
            atomicExch((unsigned long long*)&g_acc[3], 0ull);
            atomicExch(&g_count, 0u);
        }
    }
}

extern "C" void kernel_launch(void* const* d_in, const int* in_sizes, int n_in,
                              void* d_out, int out_size) {
    const float* pred = nullptr;
    const float* tbox = nullptr;
    const float* tcls = nullptr;
    const void*  mask = nullptr;
    for (int i = 0; i < n_in; i++) {
        switch (in_sizes[i]) {
            case 24084480: pred = (const float*)d_in[i]; break;  // 802816*30
            case 16056320: tcls = (const float*)d_in[i]; break;  // 802816*20
            case 3211264:  tbox = (const float*)d_in[i]; break;  // 802816*4
            case 802816:   mask = d_in[i];               break;  // 802816
        }
    }
    yolo_main_k<<<NTILES, TPB>>>(pred, tbox, tcls,
                                 (const unsigned int*)mask, (float*)d_out);
}

// round 15
// speedup vs baseline: 1.1238x; 1.1238x over previous
#include <cuda_runtime.h>
#include <cuda_bf16.h>

// ---------------------------------------------------------------------------
// YOLO loss reduction: 1024 x 28 x 28 cells -> 5 scalars.
// Round 15: REAL mask-predicated loads.  R14's ternary compiled to speculative
// LDG+SEL (zero bytes saved).  Now: hardware-predicated @p ld.global.nc.v4
// (skipped lanes fetch nothing) and NO mask barrier -- predicates come from
// tiny L1-resident mask reloads, so load issue stays fully overlapped.
// ~50% masked cells skip their cls/box words (keep conf ch4/ch9), tcls row,
// and tbox: 176 MB -> ~128 MB.
// ---------------------------------------------------------------------------

#define NTILES   3136        // 802816 / 256
#define TPB      256
#define INV_S    0.0357142857142857f   // 1/28
#define N_BATCH  1024.0

__device__ double       g_acc[4];   // cls, nbj, reg, cobj raw sums (zero-init)
__device__ unsigned int g_count;    // finished-block ticket (zero-init)

// hardware-predicated 16B load: pr==0 -> NO memory transaction, returns zeros
__device__ __forceinline__ float4 ldg128_pred(const void* p, unsigned pr) {
    float4 v = make_float4(0.f, 0.f, 0.f, 0.f);
    asm volatile(
        "{\n\t.reg .pred p;\n\t"
        "setp.ne.u32 p, %4, 0;\n\t"
        "@p ld.global.nc.v4.f32 {%0,%1,%2,%3}, [%5];\n\t}"
        : "+f"(v.x), "+f"(v.y), "+f"(v.z), "+f"(v.w)
        : "r"(pr), "l"(p));
    return v;
}

__global__ void __launch_bounds__(TPB) yolo_main_k(
    const float* __restrict__ pred,   // [802816, 30]
    const float* __restrict__ tbox,   // [802816, 4]
    const float* __restrict__ tcls,   // [802816, 20]
    const unsigned int* __restrict__ mask,  // [802816] words, truth <=> w != 0
    float*       __restrict__ out)
{
    __shared__ __align__(16) float sp[TPB * 30];   // staged pred tile
    __shared__ float red[8][4];

    const int tid   = threadIdx.x;
    const int cell0 = blockIdx.x * TPB;
    const unsigned int* mk = mask + cell0;

    // own-cell mask (register only; no smem, no barrier)
    const unsigned mw = mk[tid];
    const float    m  = (mw != 0u) ? 1.0f : 0.0f;

    // --- pred staging, hardware-predicated per float4 -----------------------
    // 1920 float4 = 128 groups x 15; group g covers cells c0=2g, c0+1.
    // r = i%15 category bitmasks: always(conf ch4/ch9) / m0-gated / m1-gated.
    {
        const float4* p4  = (const float4*)(pred + (size_t)cell0 * 30);
        float4*       sp4 = (float4*)sp;
        #pragma unroll
        for (int k = 0; k < 8; k++) {       // 1920/256 = 7.5 -> guard 8th
            int i = tid + 256 * k;
            if (i < 1920) {
                int g = i / 15;
                int r = i - 15 * g;
                uint2 m2 = *(const uint2*)(mk + 2 * g);   // masks of c0,c1 (L1)
                unsigned a = (m2.x != 0u), b = (m2.y != 0u);
                unsigned need = ((0x306u >> r) & 1u)
                              | (a & ((0xF9u >> r) & 1u))
                              | (b & ((0x7C80u >> r) & 1u));
                sp4[i] = ldg128_pred(p4 + i, need);
            }
        }
    }

    // --- tcls, hardware-predicated on owning cell's mask ---------------------
    float4 tc[5];
    float  mmj[5];
    {
        const float4* tcg4 = (const float4*)(tcls + (size_t)cell0 * 20);
        #pragma unroll
        for (int j = 0; j < 5; j++) {
            int e4 = tid + TPB * j;
            int cl = e4 / 5;
            unsigned mc = mk[cl];                  // L1-resident reload
            mmj[j] = (mc != 0u) ? 1.0f : 0.0f;
            tc[j]  = ldg128_pred(tcg4 + e4, mc);
        }
    }

    // --- tbox, predicated on own mask ----------------------------------------
    const float4 tbv = ldg128_pred((const float4*)tbox + cell0 + tid, mw);

    __syncthreads();   // sp visible

    // --- class loss: registers (tc,mmj) vs shared pred -----------------------
    float acc_cls = 0.0f;
    #pragma unroll
    for (int j = 0; j < 5; j++) {
        int e4 = tid + TPB * j;
        int cl = e4 / 5;
        int ch = 4 * (e4 - cl * 5);
        const float* pc = sp + cl * 30 + 10 + ch;
        float d0 = pc[0] - tc[j].x;
        float d1 = pc[1] - tc[j].y;
        float d2 = pc[2] - tc[j].z;
        float d3 = pc[3] - tc[j].w;
        acc_cls += mmj[j] * (d0 * d0 + d1 * d1 + d2 * d2 + d3 * d3);
    }

    // --- per-cell box terms ---------------------------------------------------
    const float* p = sp + tid * 30;

    float tcx = tbv.x * INV_S, tcy = tbv.y * INV_S;
    float thw = 0.5f * tbv.z, thh = 0.5f * tbv.w;
    float tbx1 = tcx - thw, tby1 = tcy - thh;
    float tbx2 = tcx + thw, tby2 = tcy + thh;
    float ta = (tbx2 - tbx1) * (tby2 - tby1);

    float bx1[2], by1[2], bx2[2], by2[2], iou[2], cf[2];
    #pragma unroll
    for (int b = 0; b < 2; b++) {
        float x = p[5 * b + 0], y = p[5 * b + 1];
        float w = p[5 * b + 2], h = p[5 * b + 3];
        cf[b] = p[5 * b + 4];
        float cx = x * INV_S, cy = y * INV_S;
        float hw = 0.5f * w, hh = 0.5f * h;
        bx1[b] = cx - hw; by1[b] = cy - hh;
        bx2[b] = cx + hw; by2[b] = cy + hh;
        float ltx = fmaxf(bx1[b], tbx1), lty = fmaxf(by1[b], tby1);
        float rbx = fminf(bx2[b], tbx2), rby = fminf(by2[b], tby2);
        float wi = fmaxf(rbx - ltx, 0.0f), hi = fmaxf(rby - lty, 0.0f);
        float inter = wi * hi;
        float a1 = (bx2[b] - bx1[b]) * (by2[b] - by1[b]);
        iou[b] = inter / (a1 + ta - inter);   // masked cells: 0/0 = NaN
    }

    int best = (iou[1] > iou[0]) ? 1 : 0;   // first max wins (jnp.argmax)
    float biou = iou[best];
    float bbx1 = bx1[best], bby1 = by1[best];
    float bbx2 = bx2[best], bby2 = by2[best];
    float bconf = cf[best];
    if (!(biou > 0.0f)) {                   // sanitizes NaN too
        bbx1 = bby1 = bbx2 = bby2 = 0.0f;
        bconf = 0.0f; biou = 0.0f;
    }

    float dx = bbx1 - tbx1, dy = bby1 - tby1;
    float lxy = dx * dx + dy * dy;
    float s1 = (bbx2 > 0.0f) ? sqrtf(bbx2) : 0.0f;
    float s2 = (bby2 > 0.0f) ? sqrtf(bby2) : 0.0f;
    float t1 = (tbx2 > 0.0f) ? sqrtf(tbx2) : 0.0f;
    float t2 = (tby2 > 0.0f) ? sqrtf(tby2) : 0.0f;
    float dw = s1 - t1, dh = s2 - t2;
    float lwh = dw * dw + dh * dh;

    float acc_reg  = m * (lxy + lwh);
    float dc       = bconf - biou;
    float acc_cobj = m * dc * dc;
    float acc_nbj  = (1.0f - m) * (cf[0] * cf[0] + cf[1] * cf[1]);

    // --- reduction: warp shuffle -> shared -> double atomics -----------------
    float a4[4] = { acc_cls, acc_nbj, acc_reg, acc_cobj };
    #pragma unroll
    for (int j = 0; j < 4; j++) {
        #pragma unroll
        for (int o = 16; o; o >>= 1)
            a4[j] += __shfl_down_sync(0xffffffffu, a4[j], o);
    }
    int warp = tid >> 5, lane = tid & 31;
    if (lane == 0) {
        red[warp][0] = a4[0]; red[warp][1] = a4[1];
        red[warp][2] = a4[2]; red[warp][3] = a4[3];
    }
    __syncthreads();
    if (tid == 0) {
        double s[4] = {0.0, 0.0, 0.0, 0.0};
        #pragma unroll
        for (int w = 0; w < 8; w++)
            for (int j = 0; j < 4; j++) s[j] += (double)red[w][j];
        atomicAdd(&g_acc[0], s[0]);
        atomicAdd(&g_acc[1], s[1]);
        atomicAdd(&g_acc[2], s[2]);
        atomicAdd(&g_acc[3], s[3]);

        __threadfence();
        unsigned int ticket = atomicAdd(&g_count, 1u);
        if (ticket == NTILES - 1) {
            double cls  = atomicAdd(&g_acc[0], 0.0);
            double nbj  = atomicAdd(&g_acc[1], 0.0);
            double reg  = atomicAdd(&g_acc[2], 0.0);
            double cobj = atomicAdd(&g_acc[3], 0.0);
            double cls_l  = 2.0 * cls / N_BATCH;
            double nbj_l  = 0.5 * nbj / N_BATCH;
            double reg_l  = 5.0 * reg / N_BATCH;
            double cobj_l = cobj / N_BATCH;
            out[0] = (float)(cls_l + nbj_l + reg_l + cobj_l);
            out[1] = (float)reg_l;
            out[2] = (float)cobj_l;
            out[3] = (float)nbj_l;
            out[4] = (float)cls_l;
            // self-reset for the next graph replay
            atomicExch((unsigned long long*)&g_acc[0], 0ull);
            atomicExch((unsigned long long*)&g_acc[1], 0ull);
            atomicExch((unsigned long long*)&g_acc[2], 0ull);
            atomicExch((unsigned long long*)&g_acc[3], 0ull);
            atomicExch(&g_count, 0u);
        }
    }
}

extern "C" void kernel_launch(void* const* d_in, const int* in_sizes, int n_in,
                              void* d_out, int out_size) {
    const float* pred = nullptr;
    const float* tbox = nullptr;
    const float* tcls = nullptr;
    const void*  mask = nullptr;
    for (int i = 0; i < n_in; i++) {
        switch (in_sizes[i]) {
            case 24084480: pred = (const float*)d_in[i]; break;  // 802816*30
            case 16056320: tcls = (const float*)d_in[i]; break;  // 802816*20
            case 3211264:  tbox = (const float*)d_in[i]; break;  // 802816*4
            case 802816:   mask = d_in[i];               break;  // 802816
        }
    }
    yolo_main_k<<<NTILES, TPB>>>(pred, tbox, tcls,
                                 (const unsigned int*)mask, (float*)d_out);
}

// round 16
// speedup vs baseline: 1.2971x; 1.1543x over previous
#include <cuda_runtime.h>
#include <cuda_bf16.h>

// ---------------------------------------------------------------------------
// YOLO loss reduction: 1024 x 28 x 28 cells, B=2 boxes, 20 classes -> 5 scalars
// FINAL (convergence): R3 structure -- the best-measured design (main 42.8us,
// ~98% of the empirically attainable ~4.1 TB/s read bandwidth; LDG-depth /
// TMA / prefetch / predication all failed to move the wall).  Single launch,
// one staged pred tile per block, register tcls, last-block finalize,
// self-resetting accumulators (graph-replay deterministic).
// ---------------------------------------------------------------------------

#define NTILES   3136        // 802816 / 256
#define TPB      256
#define INV_S    0.0357142857142857f   // 1/28
#define N_BATCH  1024.0

__device__ double       g_acc[4];   // cls, nbj, reg, cobj raw sums (zero-init)
__device__ unsigned int g_count;    // finished-block ticket (zero-init)

__global__ void __launch_bounds__(TPB) yolo_main_k(
    const float* __restrict__ pred,   // [802816, 30]
    const float* __restrict__ tbox,   // [802816, 4]
    const float* __restrict__ tcls,   // [802816, 20]
    const unsigned int* __restrict__ mask,  // [802816] words, truth <=> w != 0
    float*       __restrict__ out)
{
    __shared__ __align__(16) float sp[TPB * 30];   // staged pred tile
    __shared__ float smk[TPB];                     // mask as float
    __shared__ float red[8][4];

    const int tid   = threadIdx.x;
    const int cell0 = blockIdx.x * TPB;

    // --- pred staging: coalesced float4 LDG -> STS (1920 float4) ------------
    {
        const float4* p4  = (const float4*)(pred + (size_t)cell0 * 30);
        float4*       sp4 = (float4*)sp;
        #pragma unroll
        for (int i = tid; i < 1920; i += TPB) sp4[i] = p4[i];
    }

    // --- tcls prefetch into registers (in flight with pred staging) ---------
    float4 tc[5];
    {
        const float4* tcg4 = (const float4*)(tcls + (size_t)cell0 * 20);
        #pragma unroll
        for (int j = 0; j < 5; j++) tc[j] = __ldg(tcg4 + tid + TPB * j);
    }

    // --- tbox + mask: direct coalesced loads --------------------------------
    const float4 tbv = __ldg((const float4*)tbox + cell0 + tid);
    smk[tid] = (mask[cell0 + tid] != 0u) ? 1.0f : 0.0f;

    __syncthreads();   // sp + smk visible

    // --- class loss: registers (tc) vs shared pred --------------------------
    // e4 in [0,1280): cl = e4/5, ch = 4*(e4%5); float4 never crosses a cell.
    float acc_cls = 0.0f;
    #pragma unroll
    for (int j = 0; j < 5; j++) {
        int e4 = tid + TPB * j;
        int cl = e4 / 5;
        int ch = 4 * (e4 - cl * 5);
        const float* pc = sp + cl * 30 + 10 + ch;
        float mm = smk[cl];
        float d0 = pc[0] - tc[j].x;
        float d1 = pc[1] - tc[j].y;
        float d2 = pc[2] - tc[j].z;
        float d3 = pc[3] - tc[j].w;
        acc_cls += mm * (d0 * d0 + d1 * d1 + d2 * d2 + d3 * d3);
    }

    // --- per-cell box terms --------------------------------------------------
    const float* p = sp + tid * 30;
    const float  m = smk[tid];

    float tcx = tbv.x * INV_S, tcy = tbv.y * INV_S;
    float thw = 0.5f * tbv.z, thh = 0.5f * tbv.w;
    float tbx1 = tcx - thw, tby1 = tcy - thh;
    float tbx2 = tcx + thw, tby2 = tcy + thh;
    float ta = (tbx2 - tbx1) * (tby2 - tby1);

    float bx1[2], by1[2], bx2[2], by2[2], iou[2], cf[2];
    #pragma unroll
    for (int b = 0; b < 2; b++) {
        float x = p[5 * b + 0], y = p[5 * b + 1];
        float w = p[5 * b + 2], h = p[5 * b + 3];
        cf[b] = p[5 * b + 4];
        float cx = x * INV_S, cy = y * INV_S;
        float hw = 0.5f * w, hh = 0.5f * h;
        bx1[b] = cx - hw; by1[b] = cy - hh;
        bx2[b] = cx + hw; by2[b] = cy + hh;
        float ltx = fmaxf(bx1[b], tbx1), lty = fmaxf(by1[b], tby1);
        float rbx = fminf(bx2[b], tbx2), rby = fminf(by2[b], tby2);
        float wi = fmaxf(rbx - ltx, 0.0f), hi = fmaxf(rby - lty, 0.0f);
        float inter = wi * hi;
        float a1 = (bx2[b] - bx1[b]) * (by2[b] - by1[b]);
        iou[b] = inter / (a1 + ta - inter);
    }

    int best = (iou[1] > iou[0]) ? 1 : 0;   // first max wins (jnp.argmax)
    float biou = iou[best];
    float bbx1 = bx1[best], bby1 = by1[best];
    float bbx2 = bx2[best], bby2 = by2[best];
    float bconf = cf[best];
    if (!(biou > 0.0f)) {
        bbx1 = bby1 = bbx2 = bby2 = 0.0f;
        bconf = 0.0f; biou = 0.0f;
    }

    float dx = bbx1 - tbx1, dy = bby1 - tby1;
    float lxy = dx * dx + dy * dy;
    float s1 = (bbx2 > 0.0f) ? sqrtf(bbx2) : 0.0f;
    float s2 = (bby2 > 0.0f) ? sqrtf(bby2) : 0.0f;
    float t1 = (tbx2 > 0.0f) ? sqrtf(tbx2) : 0.0f;
    float t2 = (tby2 > 0.0f) ? sqrtf(tby2) : 0.0f;
    float dw = s1 - t1, dh = s2 - t2;
    float lwh = dw * dw + dh * dh;

    float acc_reg  = m * (lxy + lwh);
    float dc       = bconf - biou;
    float acc_cobj = m * dc * dc;
    float acc_nbj  = (1.0f - m) * (cf[0] * cf[0] + cf[1] * cf[1]);

    // --- reduction: warp shuffle -> shared -> double atomics ----------------
    float a4[4] = { acc_cls, acc_nbj, acc_reg, acc_cobj };
    #pragma unroll
    for (int j = 0; j < 4; j++) {
        #pragma unroll
        for (int o = 16; o; o >>= 1)
            a4[j] += __shfl_down_sync(0xffffffffu, a4[j], o);
    }
    int warp = tid >> 5, lane = tid & 31;
    if (lane == 0) {
        red[warp][0] = a4[0]; red[warp][1] = a4[1];
        red[warp][2] = a4[2]; red[warp][3] = a4[3];
    }
    __syncthreads();
    if (tid == 0) {
        double s[4] = {0.0, 0.0, 0.0, 0.0};
        #pragma unroll
        for (int w = 0; w < 8; w++)
            for (int j = 0; j < 4; j++) s[j] += (double)red[w][j];
        atomicAdd(&g_acc[0], s[0]);
        atomicAdd(&g_acc[1], s[1]);
        atomicAdd(&g_acc[2], s[2]);
        atomicAdd(&g_acc[3], s[3]);

        __threadfence();
        unsigned int ticket = atomicAdd(&g_count, 1u);
        if (ticket == NTILES - 1) {
            // all blocks' g_acc atomics precede their ticket increment
            double cls  = atomicAdd(&g_acc[0], 0.0);
            double nbj  = atomicAdd(&g_acc[1], 0.0);
            double reg  = atomicAdd(&g_acc[2], 0.0);
            double cobj = atomicAdd(&g_acc[3], 0.0);
            double cls_l  = 2.0 * cls / N_BATCH;
            double nbj_l  = 0.5 * nbj / N_BATCH;
            double reg_l  = 5.0 * reg / N_BATCH;
            double cobj_l = cobj / N_BATCH;
            out[0] = (float)(cls_l + nbj_l + reg_l + cobj_l);
            out[1] = (float)reg_l;
            out[2] = (float)cobj_l;
            out[3] = (float)nbj_l;
            out[4] = (float)cls_l;
            // self-reset for the next graph replay
            atomicExch((unsigned long long*)&g_acc[0], 0ull);
            atomicExch((unsigned long long*)&g_acc[1], 0ull);
            atomicExch((unsigned long long*)&g_acc[2], 0ull);
            atomicExch((unsigned long long*)&g_acc[3], 0ull);
            atomicExch(&g_count, 0u);
        }
    }
}

extern "C" void kernel_launch(void* const* d_in, const int* in_sizes, int n_in,
                              void* d_out, int out_size) {
    const float* pred = nullptr;
    const float* tbox = nullptr;
    const float* tcls = nullptr;
    const void*  mask = nullptr;
    for (int i = 0; i < n_in; i++) {
        switch (in_sizes[i]) {
            case 24084480: pred = (const float*)d_in[i]; break;  // 802816*30
            case 16056320: tcls = (const float*)d_in[i]; break;  // 802816*20
            case 3211264:  tbox = (const float*)d_in[i]; break;  // 802816*4
            case 802816:   mask = d_in[i];               break;  // 802816
        }
    }
    yolo_main_k<<<NTILES, TPB>>>(pred, tbox, tcls,
                                 (const unsigned int*)mask, (float*)d_out);
}

// round 17
// speedup vs baseline: 1.3285x; 1.0241x over previous
#include <cuda_runtime.h>
#include <cuda_bf16.h>

// ---------------------------------------------------------------------------
// YOLO loss reduction: 1024 x 28 x 28 cells, B=2 boxes, 20 classes -> 5 scalars
// Round 17: ALL traffic via the non-coherent (.nc / LDG.E.CI) path.  R16
// showed the long-standing 4.1 TB/s wall was coherent-LDG-path-specific:
// moving tcls+tbox to __ldg raised achieved BW to 4.54 TB/s.  Now pred (96 MB,
// 55% of traffic) and mask go .nc too.  Structure otherwise = best-measured
// R3/R16: staged pred tile, register tcls, last-block finalize, self-reset.
// ---------------------------------------------------------------------------

#define NTILES   3136        // 802816 / 256
#define TPB      256
#define INV_S    0.0357142857142857f   // 1/28
#define N_BATCH  1024.0

__device__ double       g_acc[4];   // cls, nbj, reg, cobj raw sums (zero-init)
__device__ unsigned int g_count;    // finished-block ticket (zero-init)

__global__ void __launch_bounds__(TPB) yolo_main_k(
    const float* __restrict__ pred,   // [802816, 30]
    const float* __restrict__ tbox,   // [802816, 4]
    const float* __restrict__ tcls,   // [802816, 20]
    const unsigned int* __restrict__ mask,  // [802816] words, truth <=> w != 0
    float*       __restrict__ out)
{
    __shared__ __align__(16) float sp[TPB * 30];   // staged pred tile
    __shared__ float smk[TPB];                     // mask as float
    __shared__ float red[8][4];

    const int tid   = threadIdx.x;
    const int cell0 = blockIdx.x * TPB;

    // --- pred staging: coalesced .nc float4 LDG -> STS (1920 float4) --------
    {
        const float4* p4  = (const float4*)(pred + (size_t)cell0 * 30);
        float4*       sp4 = (float4*)sp;
        #pragma unroll
        for (int i = tid; i < 1920; i += TPB) sp4[i] = __ldg(p4 + i);
    }

    // --- tcls prefetch into registers (.nc, in flight with pred staging) ----
    float4 tc[5];
    {
        const float4* tcg4 = (const float4*)(tcls + (size_t)cell0 * 20);
        #pragma unroll
        for (int j = 0; j < 5; j++) tc[j] = __ldg(tcg4 + tid + TPB * j);
    }

    // --- tbox + mask: direct coalesced .nc loads -----------------------------
    const float4 tbv = __ldg((const float4*)tbox + cell0 + tid);
    smk[tid] = (__ldg(mask + cell0 + tid) != 0u) ? 1.0f : 0.0f;

    __syncthreads();   // sp + smk visible

    // --- class loss: registers (tc) vs shared pred --------------------------
    // e4 in [0,1280): cl = e4/5, ch = 4*(e4%5); float4 never crosses a cell.
    float acc_cls = 0.0f;
    #pragma unroll
    for (int j = 0; j < 5; j++) {
        int e4 = tid + TPB * j;
        int cl = e4 / 5;
        int ch = 4 * (e4 - cl * 5);
        const float* pc = sp + cl * 30 + 10 + ch;
        float mm = smk[cl];
        float d0 = pc[0] - tc[j].x;
        float d1 = pc[1] - tc[j].y;
        float d2 = pc[2] - tc[j].z;
        float d3 = pc[3] - tc[j].w;
        acc_cls += mm * (d0 * d0 + d1 * d1 + d2 * d2 + d3 * d3);
    }

    // --- per-cell box terms --------------------------------------------------
    const float* p = sp + tid * 30;
    const float  m = smk[tid];

    float tcx = tbv.x * INV_S, tcy = tbv.y * INV_S;
    float thw = 0.5f * tbv.z, thh = 0.5f * tbv.w;
    float tbx1 = tcx - thw, tby1 = tcy - thh;
    float tbx2 = tcx + thw, tby2 = tcy + thh;
    float ta = (tbx2 - tbx1) * (tby2 - tby1);

    float bx1[2], by1[2], bx2[2], by2[2], iou[2], cf[2];
    #pragma unroll
    for (int b = 0; b < 2; b++) {
        float x = p[5 * b + 0], y = p[5 * b + 1];
        float w = p[5 * b + 2], h = p[5 * b + 3];
        cf[b] = p[5 * b + 4];
        float cx = x * INV_S, cy = y * INV_S;
        float hw = 0.5f * w, hh = 0.5f * h;
        bx1[b] = cx - hw; by1[b] = cy - hh;
        bx2[b] = cx + hw; by2[b] = cy + hh;
        float ltx = fmaxf(bx1[b], tbx1), lty = fmaxf(by1[b], tby1);
        float rbx = fminf(bx2[b], tbx2), rby = fminf(by2[b], tby2);
        float wi = fmaxf(rbx - ltx, 0.0f), hi = fmaxf(rby - lty, 0.0f);
        float inter = wi * hi;
        float a1 = (bx2[b] - bx1[b]) * (by2[b] - by1[b]);
        iou[b] = inter / (a1 + ta - inter);
    }

    int best = (iou[1] > iou[0]) ? 1 : 0;   // first max wins (jnp.argmax)
    float biou = iou[best];
    float bbx1 = bx1[best], bby1 = by1[best];
    float bbx2 = bx2[best], bby2 = by2[best];
    float bconf = cf[best];
    if (!(biou > 0.0f)) {
        bbx1 = bby1 = bbx2 = bby2 = 0.0f;
        bconf = 0.0f; biou = 0.0f;
    }

    float dx = bbx1 - tbx1, dy = bby1 - tby1;
    float lxy = dx * dx + dy * dy;
    float s1 = (bbx2 > 0.0f) ? sqrtf(bbx2) : 0.0f;
    float s2 = (bby2 > 0.0f) ? sqrtf(bby2) : 0.0f;
    float t1 = (tbx2 > 0.0f) ? sqrtf(tbx2) : 0.0f;
    float t2 = (tby2 > 0.0f) ? sqrtf(tby2) : 0.0f;
    float dw = s1 - t1, dh = s2 - t2;
    float lwh = dw * dw + dh * dh;

    float acc_reg  = m * (lxy + lwh);
    float dc       = bconf - biou;
    float acc_cobj = m * dc * dc;
    float acc_nbj  = (1.0f - m) * (cf[0] * cf[0] + cf[1] * cf[1]);

    // --- reduction: warp shuffle -> shared -> double atomics ----------------
    float a4[4] = { acc_cls, acc_nbj, acc_reg, acc_cobj };
    #pragma unroll
    for (int j = 0; j < 4; j++) {
        #pragma unroll
        for (int o = 16; o; o >>= 1)
            a4[j] += __shfl_down_sync(0xffffffffu, a4[j], o);
    }
    int warp = tid >> 5, lane = tid & 31;
    if (lane == 0) {
        red[warp][0] = a4[0]; red[warp][1] = a4[1];
        red[warp][2] = a4[2]; red[warp][3] = a4[3];
    }
    __syncthreads();
    if (tid == 0) {
        double s[4] = {0.0, 0.0, 0.0, 0.0};
        #pragma unroll
        for (int w = 0; w < 8; w++)
            for (int j = 0; j < 4; j++) s[j] += (double)red[w][j];
        atomicAdd(&g_acc[0], s[0]);
        atomicAdd(&g_acc[1], s[1]);
        atomicAdd(&g_acc[2], s[2]);
        atomicAdd(&g_acc[3], s[3]);

        __threadfence();
        unsigned int ticket = atomicAdd(&g_count, 1u);
        if (ticket == NTILES - 1) {
            // all blocks' g_acc atomics precede their ticket increment
            double cls  = atomicAdd(&g_acc[0], 0.0);
            double nbj  = atomicAdd(&g_acc[1], 0.0);
            double reg  = atomicAdd(&g_acc[2], 0.0);
            double cobj = atomicAdd(&g_acc[3], 0.0);
            double cls_l  = 2.0 * cls / N_BATCH;
            double nbj_l  = 0.5 * nbj / N_BATCH;
            double reg_l  = 5.0 * reg / N_BATCH;
            double cobj_l = cobj / N_BATCH;
            out[0] = (float)(cls_l + nbj_l + reg_l + cobj_l);
            out[1] = (float)reg_l;
            out[2] = (float)cobj_l;
            out[3] = (float)nbj_l;
            out[4] = (float)cls_l;
            // self-reset for the next graph replay
            atomicExch((unsigned long long*)&g_acc[0], 0ull);
            atomicExch((unsigned long long*)&g_acc[1], 0ull);
            atomicExch((unsigned long long*)&g_acc[2], 0ull);
            atomicExch((unsigned long long*)&g_acc[3], 0ull);
            atomicExch(&g_count, 0u);
        }
    }
}

extern "C" void kernel_launch(void* const* d_in, const int* in_sizes, int n_in,
                              void* d_out, int out_size) {
    const float* pred = nullptr;
    const float* tbox = nullptr;
    const float* tcls = nullptr;
    const void*  mask = nullptr;
    for (int i = 0; i < n_in; i++) {
        switch (in_sizes[i]) {
            case 24084480: pred = (const float*)d_in[i]; break;  // 802816*30
            case 16056320: tcls = (const float*)d_in[i]; break;  // 802816*20
            case 3211264:  tbox = (const float*)d_in[i]; break;  // 802816*4
            case 802816:   mask = d_in[i];               break;  // 802816
        }
    }
    yolo_main_k<<<NTILES, TPB>>>(pred, tbox, tcls,
                                 (const unsigned int*)mask, (float*)d_out);
}